// round 1
// baseline (speedup 1.0000x reference)
#include <cuda_runtime.h>
#include <cuda_bf16.h>

#define N_NODES 50000
#define N_EDGES 600000
#define DIM     128
#define LN_EPS  1e-5f

// Scratch (device globals: allocation-free per harness rules)
__device__ float g_agg[N_NODES * DIM];
__device__ float g_degout[N_NODES];
__device__ float g_degin[N_NODES];
__device__ float g_outnorm[N_NODES];
__device__ float g_innorm[N_NODES];

// ---------------------------------------------------------------------------
// Degree counting: one thread per edge, float atomic counts (exact < 2^24)
// ---------------------------------------------------------------------------
__global__ void deg_kernel(const int* __restrict__ src, const int* __restrict__ dst) {
    int e = blockIdx.x * blockDim.x + threadIdx.x;
    if (e < N_EDGES) {
        atomicAdd(&g_degout[src[e]], 1.0f);
        atomicAdd(&g_degin[dst[e]], 1.0f);
    }
}

// ---------------------------------------------------------------------------
// norm = rsqrt(max(deg, 1))
// ---------------------------------------------------------------------------
__global__ void norm_kernel() {
    int i = blockIdx.x * blockDim.x + threadIdx.x;
    if (i < N_NODES) {
        g_outnorm[i] = rsqrtf(fmaxf(g_degout[i], 1.0f));
        g_innorm[i]  = rsqrtf(fmaxf(g_degin[i], 1.0f));
    }
}

// ---------------------------------------------------------------------------
// Edge aggregation: one warp per edge, float4 per lane.
// agg[dst] += feat[src] * outnorm[src], via vector reduction atomics
// (red.global.add.v4.f32 — no return value, one transaction per 16B).
// feat + agg both fit in L2, so this should be LTS-bound, not HBM-bound.
// ---------------------------------------------------------------------------
__global__ void edge_kernel(const int* __restrict__ src, const int* __restrict__ dst,
                            const float* __restrict__ feat) {
    int t = blockIdx.x * blockDim.x + threadIdx.x;
    int e = t >> 5;
    int lane = t & 31;
    if (e < N_EDGES) {
        int s = src[e];
        int d = dst[e];
        float sc = g_outnorm[s];
        float4 v = reinterpret_cast<const float4*>(feat)[s * (DIM / 4) + lane];
        v.x *= sc; v.y *= sc; v.z *= sc; v.w *= sc;
        float* p = &g_agg[d * DIM + lane * 4];
        asm volatile("red.global.add.v4.f32 [%0], {%1, %2, %3, %4};"
                     :: "l"(p), "f"(v.x), "f"(v.y), "f"(v.z), "f"(v.w)
                     : "memory");
    }
}

// ---------------------------------------------------------------------------
// Fused GEMM + bias + LayerNorm + ReLU.
//
// out = relu(LN( (agg @ fc_w + fc_b) * in_norm + feat @ res_w ))
//     = relu(LN( (agg*in_norm) @ fc_w + fc_b*in_norm + feat @ res_w ))
//
// Virtual A = [agg * in_norm | feat]   (M=50000, K=256)
// Virtual B = [fc_w ; res_w]           (K=256, N=128)
//
// Tiling: BM=64, BN=128, BK=16, 256 threads (ty 0..15 x tx 0..15),
// per-thread microtile 4 rows x 8 cols. LN epilogue through a 64x132 SMEM tile.
// ---------------------------------------------------------------------------
#define BM 64
#define BN 128
#define BK 16
#define CS_STRIDE 132   // padded to avoid bank conflicts

__global__ __launch_bounds__(256) void gemm_ln_kernel(
    const float* __restrict__ feat,
    const float* __restrict__ fc_w,
    const float* __restrict__ fc_b,
    const float* __restrict__ res_w,
    const float* __restrict__ ln_g,
    const float* __restrict__ ln_b,
    float* __restrict__ out)
{
    __shared__ __align__(16) float As[BK][BM];        // A^T tile
    __shared__ __align__(16) float Bs[BK][BN];
    __shared__ __align__(16) float Cs[BM * CS_STRIDE];

    const int tid = threadIdx.x;
    const int tx = tid & 15;          // column group (8 cols)
    const int ty = tid >> 4;          // row group (4 rows)
    const int bm0 = blockIdx.x * BM;

    float acc[4][8];
#pragma unroll
    for (int i = 0; i < 4; i++)
#pragma unroll
        for (int j = 0; j < 8; j++) acc[i][j] = 0.0f;

    // A-load mapping: r = tid>>2 (0..63 rows), kq = tid&3 (float4 along k)
    const int a_r  = tid >> 2;
    const int a_kq = tid & 3;
    const int a_row_g = bm0 + a_r;
    // B-load mapping: kb_row = tid>>5 (0..7), col = (tid&31)*4
    const int b_k   = tid >> 5;
    const int b_col = (tid & 31) * 4;

    for (int kt = 0; kt < 16; kt++) {
        const bool first_half = (kt < 8);
        const int kb = first_half ? kt * BK : (kt - 8) * BK;
        const float* Asrc = first_half ? g_agg : feat;
        const float* Bsrc = first_half ? fc_w : res_w;

        // ---- load A tile (64 rows x 16 k), transpose into As[k][row] ----
        float4 a = make_float4(0.f, 0.f, 0.f, 0.f);
        if (a_row_g < N_NODES) {
            a = reinterpret_cast<const float4*>(Asrc + a_row_g * DIM + kb)[a_kq];
            if (first_half) {
                float s = g_innorm[a_row_g];
                a.x *= s; a.y *= s; a.z *= s; a.w *= s;
            }
        }
        As[a_kq * 4 + 0][a_r] = a.x;
        As[a_kq * 4 + 1][a_r] = a.y;
        As[a_kq * 4 + 2][a_r] = a.z;
        As[a_kq * 4 + 3][a_r] = a.w;

        // ---- load B tile (16 k x 128 cols) ----
        {
            float4 b0 = *reinterpret_cast<const float4*>(Bsrc + (kb + b_k) * DIM + b_col);
            float4 b1 = *reinterpret_cast<const float4*>(Bsrc + (kb + b_k + 8) * DIM + b_col);
            *reinterpret_cast<float4*>(&Bs[b_k][b_col]) = b0;
            *reinterpret_cast<float4*>(&Bs[b_k + 8][b_col]) = b1;
        }
        __syncthreads();

#pragma unroll
        for (int kk = 0; kk < BK; kk++) {
            float4 av = *reinterpret_cast<const float4*>(&As[kk][ty * 4]);
            float4 bv0 = *reinterpret_cast<const float4*>(&Bs[kk][tx * 8]);
            float4 bv1 = *reinterpret_cast<const float4*>(&Bs[kk][tx * 8 + 4]);
            float ar[4] = {av.x, av.y, av.z, av.w};
            float br[8] = {bv0.x, bv0.y, bv0.z, bv0.w, bv1.x, bv1.y, bv1.z, bv1.w};
#pragma unroll
            for (int i = 0; i < 4; i++)
#pragma unroll
                for (int j = 0; j < 8; j++)
                    acc[i][j] = fmaf(ar[i], br[j], acc[i][j]);
        }
        __syncthreads();
    }

    // ---- bias (scaled by in_norm) + stage rows into Cs for LayerNorm ----
    {
        float bias[8];
        float4 fb0 = *reinterpret_cast<const float4*>(fc_b + tx * 8);
        float4 fb1 = *reinterpret_cast<const float4*>(fc_b + tx * 8 + 4);
        bias[0] = fb0.x; bias[1] = fb0.y; bias[2] = fb0.z; bias[3] = fb0.w;
        bias[4] = fb1.x; bias[5] = fb1.y; bias[6] = fb1.z; bias[7] = fb1.w;
#pragma unroll
        for (int i = 0; i < 4; i++) {
            int row_l = ty * 4 + i;
            int row_g = bm0 + row_l;
            float innm = (row_g < N_NODES) ? g_innorm[row_g] : 0.0f;
            float4 c0, c1;
            c0.x = acc[i][0] + innm * bias[0];
            c0.y = acc[i][1] + innm * bias[1];
            c0.z = acc[i][2] + innm * bias[2];
            c0.w = acc[i][3] + innm * bias[3];
            c1.x = acc[i][4] + innm * bias[4];
            c1.y = acc[i][5] + innm * bias[5];
            c1.z = acc[i][6] + innm * bias[6];
            c1.w = acc[i][7] + innm * bias[7];
            *reinterpret_cast<float4*>(&Cs[row_l * CS_STRIDE + tx * 8]) = c0;
            *reinterpret_cast<float4*>(&Cs[row_l * CS_STRIDE + tx * 8 + 4]) = c1;
        }
    }
    __syncthreads();

    // ---- LayerNorm + ReLU epilogue: 8 warps, 8 rows each ----
    {
        const int warp = tid >> 5;
        const int lane = tid & 31;
        float4 g4 = *reinterpret_cast<const float4*>(ln_g + lane * 4);
        float4 bb4 = *reinterpret_cast<const float4*>(ln_b + lane * 4);
        for (int rr = warp; rr < BM; rr += 8) {
            int row_g = bm0 + rr;
            if (row_g >= N_NODES) break;
            float4 v = *reinterpret_cast<const float4*>(&Cs[rr * CS_STRIDE + lane * 4]);
            float s  = v.x + v.y + v.z + v.w;
            float s2 = v.x * v.x + v.y * v.y + v.z * v.z + v.w * v.w;
#pragma unroll
            for (int o = 16; o > 0; o >>= 1) {
                s  += __shfl_xor_sync(0xFFFFFFFFu, s, o);
                s2 += __shfl_xor_sync(0xFFFFFFFFu, s2, o);
            }
            float mu = s * (1.0f / DIM);
            float var = s2 * (1.0f / DIM) - mu * mu;
            float inv = rsqrtf(var + LN_EPS);
            float4 r;
            r.x = fmaxf((v.x - mu) * inv * g4.x + bb4.x, 0.0f);
            r.y = fmaxf((v.y - mu) * inv * g4.y + bb4.y, 0.0f);
            r.z = fmaxf((v.z - mu) * inv * g4.z + bb4.z, 0.0f);
            r.w = fmaxf((v.w - mu) * inv * g4.w + bb4.w, 0.0f);
            reinterpret_cast<float4*>(out)[row_g * (DIM / 4) + lane] = r;
        }
    }
}

// ---------------------------------------------------------------------------
extern "C" void kernel_launch(void* const* d_in, const int* in_sizes, int n_in,
                              void* d_out, int out_size) {
    const float* feat  = (const float*)d_in[0];
    const int*   src   = (const int*)d_in[1];
    const int*   dst   = (const int*)d_in[2];
    const float* fc_w  = (const float*)d_in[3];
    const float* fc_b  = (const float*)d_in[4];
    const float* res_w = (const float*)d_in[5];
    const float* ln_g  = (const float*)d_in[6];
    const float* ln_b  = (const float*)d_in[7];
    float* out = (float*)d_out;

    void *agg_p, *dout_p, *din_p;
    cudaGetSymbolAddress(&agg_p, g_agg);
    cudaGetSymbolAddress(&dout_p, g_degout);
    cudaGetSymbolAddress(&din_p, g_degin);
    cudaMemsetAsync(agg_p, 0, sizeof(float) * N_NODES * DIM);
    cudaMemsetAsync(dout_p, 0, sizeof(float) * N_NODES);
    cudaMemsetAsync(din_p, 0, sizeof(float) * N_NODES);

    deg_kernel<<<(N_EDGES + 255) / 256, 256>>>(src, dst);
    norm_kernel<<<(N_NODES + 255) / 256, 256>>>();
    edge_kernel<<<(N_EDGES * 32) / 256, 256>>>(src, dst, feat);
    gemm_ln_kernel<<<(N_NODES + BM - 1) / BM, 256>>>(feat, fc_w, fc_b, res_w,
                                                     ln_g, ln_b, out);
}

// round 2
// speedup vs baseline: 1.0070x; 1.0070x over previous
#include <cuda_runtime.h>
#include <cuda_bf16.h>

#define N_NODES 50000
#define N_EDGES 600000
#define DIM     128
#define LN_EPS  1e-5f

// Scratch (device globals: allocation-free per harness rules)
__device__ float g_agg[N_NODES * DIM];
__device__ float g_degout[N_NODES];
__device__ float g_degin[N_NODES];
__device__ float g_outnorm[N_NODES];
__device__ float g_innorm[N_NODES];

// ---------------------------------------------------------------------------
// Packed f32x2 helpers (sm_100+): FFMA2 doubles fp32 FMA throughput.
// ---------------------------------------------------------------------------
__device__ __forceinline__ unsigned long long pack_dup(float a) {
    unsigned long long r;
    asm("mov.b64 %0, {%1, %1};" : "=l"(r) : "f"(a));
    return r;
}
__device__ __forceinline__ void fma2(unsigned long long& d,
                                     unsigned long long a,
                                     unsigned long long b) {
    asm("fma.rn.f32x2 %0, %1, %2, %0;" : "+l"(d) : "l"(a), "l"(b));
}
__device__ __forceinline__ void unpack2(unsigned long long v, float& lo, float& hi) {
    asm("mov.b64 {%0, %1}, %2;" : "=f"(lo), "=f"(hi) : "l"(v));
}

// ---------------------------------------------------------------------------
// Degree counting
// ---------------------------------------------------------------------------
__global__ void deg_kernel(const int* __restrict__ src, const int* __restrict__ dst) {
    int e = blockIdx.x * blockDim.x + threadIdx.x;
    if (e < N_EDGES) {
        atomicAdd(&g_degout[src[e]], 1.0f);
        atomicAdd(&g_degin[dst[e]], 1.0f);
    }
}

__global__ void norm_kernel() {
    int i = blockIdx.x * blockDim.x + threadIdx.x;
    if (i < N_NODES) {
        g_outnorm[i] = rsqrtf(fmaxf(g_degout[i], 1.0f));
        g_innorm[i]  = rsqrtf(fmaxf(g_degin[i], 1.0f));
    }
}

// ---------------------------------------------------------------------------
// Edge aggregation: one warp per edge, red.global.add.v4.f32 (L2-resident)
// ---------------------------------------------------------------------------
__global__ void edge_kernel(const int* __restrict__ src, const int* __restrict__ dst,
                            const float* __restrict__ feat) {
    int t = blockIdx.x * blockDim.x + threadIdx.x;
    int e = t >> 5;
    int lane = t & 31;
    if (e < N_EDGES) {
        int s = src[e];
        int d = dst[e];
        float sc = g_outnorm[s];
        float4 v = reinterpret_cast<const float4*>(feat)[s * (DIM / 4) + lane];
        v.x *= sc; v.y *= sc; v.z *= sc; v.w *= sc;
        float* p = &g_agg[d * DIM + lane * 4];
        asm volatile("red.global.add.v4.f32 [%0], {%1, %2, %3, %4};"
                     :: "l"(p), "f"(v.x), "f"(v.y), "f"(v.z), "f"(v.w)
                     : "memory");
    }
}

// ---------------------------------------------------------------------------
// Fused GEMM (f32x2 FFMA2) + bias + LayerNorm + ReLU, all in registers.
//
// out = relu(LN( (agg*in_norm) @ fc_w + fc_b*in_norm + feat @ res_w ))
// Virtual A = [agg*in_norm | feat]  (M=50000, K=256), B = [fc_w ; res_w]
//
// BM=64, BN=128, BK=16, 256 threads: tx=tid&15 owns 8 cols, ty=tid>>4 owns
// 4 rows. acc = 4 rows x 4 col-pairs in f32x2. Double-buffered SMEM,
// one sync per k-tile. LN via half-warp shuffle (row owners = half warp).
// ---------------------------------------------------------------------------
#define BM 64
#define BN 128
#define BK 16
#define AS_STRIDE 20   // BK + 4 pad, keeps 16B alignment, avoids conflicts

__global__ __launch_bounds__(256, 3) void gemm_ln_kernel(
    const float* __restrict__ feat,
    const float* __restrict__ fc_w,
    const float* __restrict__ fc_b,
    const float* __restrict__ res_w,
    const float* __restrict__ ln_g,
    const float* __restrict__ ln_b,
    float* __restrict__ out)
{
    __shared__ __align__(16) float As[2][BM][AS_STRIDE];  // row-major A tile
    __shared__ __align__(16) float Bs[2][BK][BN];

    const int tid = threadIdx.x;
    const int tx = tid & 15;       // column group (8 cols)
    const int ty = tid >> 4;       // row group (4 rows)
    const int bm0 = blockIdx.x * BM;

    // A-load mapping: ar = row (0..63), akq = float4 index along k (0..3)
    const int ar  = tid >> 2;
    const int akq = tid & 3;
    const int a_row_g = bm0 + ar;
    const bool a_ok = (a_row_g < N_NODES);
    const float innm_a = a_ok ? g_innorm[a_row_g] : 0.0f;
    // B-load mapping: bk = k row (0..15), bc = column (16 threads x 8 cols)
    const int bk = tid >> 4;
    const int bc = (tid & 15) * 8;

    unsigned long long acc[4][4];
#pragma unroll
    for (int i = 0; i < 4; i++)
#pragma unroll
        for (int j = 0; j < 4; j++) acc[i][j] = 0ULL;

    float4 sa, sb0, sb1;

    auto load_tile = [&](int kt) {
        const bool fh = (kt < 8);
        const int kb = (fh ? kt : kt - 8) * BK;
        const float* Ap = fh ? g_agg : feat;
        const float* Bp = fh ? fc_w : res_w;
        if (a_ok) {
            sa = *reinterpret_cast<const float4*>(Ap + a_row_g * DIM + kb + akq * 4);
            if (fh) { sa.x *= innm_a; sa.y *= innm_a; sa.z *= innm_a; sa.w *= innm_a; }
        } else {
            sa = make_float4(0.f, 0.f, 0.f, 0.f);
        }
        sb0 = *reinterpret_cast<const float4*>(Bp + (kb + bk) * DIM + bc);
        sb1 = *reinterpret_cast<const float4*>(Bp + (kb + bk) * DIM + bc + 4);
    };
    auto store_tile = [&](int buf) {
        *reinterpret_cast<float4*>(&As[buf][ar][akq * 4]) = sa;
        *reinterpret_cast<float4*>(&Bs[buf][bk][bc]) = sb0;
        *reinterpret_cast<float4*>(&Bs[buf][bk][bc + 4]) = sb1;
    };

    load_tile(0);
    store_tile(0);
    __syncthreads();

    for (int kt = 0; kt < 16; kt++) {
        const int cur = kt & 1;
        if (kt < 15) load_tile(kt + 1);

#pragma unroll
        for (int kk = 0; kk < BK; kk++) {
            unsigned long long bp[4];
            float4 b0 = *reinterpret_cast<const float4*>(&Bs[cur][kk][tx * 8]);
            float4 b1 = *reinterpret_cast<const float4*>(&Bs[cur][kk][tx * 8 + 4]);
            asm("mov.b64 %0, {%1, %2};" : "=l"(bp[0]) : "f"(b0.x), "f"(b0.y));
            asm("mov.b64 %0, {%1, %2};" : "=l"(bp[1]) : "f"(b0.z), "f"(b0.w));
            asm("mov.b64 %0, {%1, %2};" : "=l"(bp[2]) : "f"(b1.x), "f"(b1.y));
            asm("mov.b64 %0, {%1, %2};" : "=l"(bp[3]) : "f"(b1.z), "f"(b1.w));
#pragma unroll
            for (int i = 0; i < 4; i++) {
                unsigned long long ad = pack_dup(As[cur][ty * 4 + i][kk]);
                fma2(acc[i][0], ad, bp[0]);
                fma2(acc[i][1], ad, bp[1]);
                fma2(acc[i][2], ad, bp[2]);
                fma2(acc[i][3], ad, bp[3]);
            }
        }

        if (kt < 15) {
            store_tile(cur ^ 1);
            __syncthreads();
        }
    }

    // ---- epilogue: bias*in_norm, LayerNorm stats via half-warp shuffle ----
    float bias[8], gam[8], bet[8];
    {
        float4 t0 = *reinterpret_cast<const float4*>(fc_b + tx * 8);
        float4 t1 = *reinterpret_cast<const float4*>(fc_b + tx * 8 + 4);
        bias[0]=t0.x; bias[1]=t0.y; bias[2]=t0.z; bias[3]=t0.w;
        bias[4]=t1.x; bias[5]=t1.y; bias[6]=t1.z; bias[7]=t1.w;
        t0 = *reinterpret_cast<const float4*>(ln_g + tx * 8);
        t1 = *reinterpret_cast<const float4*>(ln_g + tx * 8 + 4);
        gam[0]=t0.x; gam[1]=t0.y; gam[2]=t0.z; gam[3]=t0.w;
        gam[4]=t1.x; gam[5]=t1.y; gam[6]=t1.z; gam[7]=t1.w;
        t0 = *reinterpret_cast<const float4*>(ln_b + tx * 8);
        t1 = *reinterpret_cast<const float4*>(ln_b + tx * 8 + 4);
        bet[0]=t0.x; bet[1]=t0.y; bet[2]=t0.z; bet[3]=t0.w;
        bet[4]=t1.x; bet[5]=t1.y; bet[6]=t1.z; bet[7]=t1.w;
    }

#pragma unroll
    for (int i = 0; i < 4; i++) {
        int row_g = bm0 + ty * 4 + i;
        if (row_g >= N_NODES) break;
        float innm = g_innorm[row_g];

        float c[8];
#pragma unroll
        for (int j = 0; j < 4; j++) {
            float lo, hi;
            unpack2(acc[i][j], lo, hi);
            c[j * 2]     = lo + innm * bias[j * 2];
            c[j * 2 + 1] = hi + innm * bias[j * 2 + 1];
        }
        float s = 0.f, s2 = 0.f;
#pragma unroll
        for (int j = 0; j < 8; j++) { s += c[j]; s2 += c[j] * c[j]; }
        // reduce across the 16 column-owner lanes (a half warp)
#pragma unroll
        for (int o = 8; o > 0; o >>= 1) {
            s  += __shfl_xor_sync(0xFFFFFFFFu, s, o);
            s2 += __shfl_xor_sync(0xFFFFFFFFu, s2, o);
        }
        float mu  = s * (1.0f / DIM);
        float var = s2 * (1.0f / DIM) - mu * mu;
        float inv = rsqrtf(var + LN_EPS);

        float4 r0, r1;
        r0.x = fmaxf((c[0] - mu) * inv * gam[0] + bet[0], 0.f);
        r0.y = fmaxf((c[1] - mu) * inv * gam[1] + bet[1], 0.f);
        r0.z = fmaxf((c[2] - mu) * inv * gam[2] + bet[2], 0.f);
        r0.w = fmaxf((c[3] - mu) * inv * gam[3] + bet[3], 0.f);
        r1.x = fmaxf((c[4] - mu) * inv * gam[4] + bet[4], 0.f);
        r1.y = fmaxf((c[5] - mu) * inv * gam[5] + bet[5], 0.f);
        r1.z = fmaxf((c[6] - mu) * inv * gam[6] + bet[6], 0.f);
        r1.w = fmaxf((c[7] - mu) * inv * gam[7] + bet[7], 0.f);
        *reinterpret_cast<float4*>(out + row_g * DIM + tx * 8) = r0;
        *reinterpret_cast<float4*>(out + row_g * DIM + tx * 8 + 4) = r1;
    }
}

// ---------------------------------------------------------------------------
extern "C" void kernel_launch(void* const* d_in, const int* in_sizes, int n_in,
                              void* d_out, int out_size) {
    const float* feat  = (const float*)d_in[0];
    const int*   src   = (const int*)d_in[1];
    const int*   dst   = (const int*)d_in[2];
    const float* fc_w  = (const float*)d_in[3];
    const float* fc_b  = (const float*)d_in[4];
    const float* res_w = (const float*)d_in[5];
    const float* ln_g  = (const float*)d_in[6];
    const float* ln_b  = (const float*)d_in[7];
    float* out = (float*)d_out;

    void *agg_p, *dout_p, *din_p;
    cudaGetSymbolAddress(&agg_p, g_agg);
    cudaGetSymbolAddress(&dout_p, g_degout);
    cudaGetSymbolAddress(&din_p, g_degin);
    cudaMemsetAsync(agg_p, 0, sizeof(float) * N_NODES * DIM);
    cudaMemsetAsync(dout_p, 0, sizeof(float) * N_NODES);
    cudaMemsetAsync(din_p, 0, sizeof(float) * N_NODES);

    deg_kernel<<<(N_EDGES + 255) / 256, 256>>>(src, dst);
    norm_kernel<<<(N_NODES + 255) / 256, 256>>>();
    edge_kernel<<<(N_EDGES * 32) / 256, 256>>>(src, dst, feat);
    gemm_ln_kernel<<<(N_NODES + BM - 1) / BM, 256>>>(feat, fc_w, fc_b, res_w,
                                                     ln_g, ln_b, out);
}

// round 4
// speedup vs baseline: 1.6966x; 1.6847x over previous
#include <cuda_runtime.h>
#include <cuda_bf16.h>
#include <cstdint>

#define N_NODES 50000
#define N_EDGES 600000
#define DIM     128
#define LN_EPS  1e-5f

// ---------------------------------------------------------------------------
// Scratch (device globals: allocation-free per harness rules)
// ---------------------------------------------------------------------------
__device__ float g_agg[N_NODES * DIM];
__device__ float g_degout[N_NODES];
__device__ float g_degin[N_NODES];
__device__ float g_outnorm[N_NODES];
__device__ float g_innorm[N_NODES];
// B tiles (bf16, plain [n][k] layout): [h0_hi | h0_lo | h1_hi | h1_lo]
__device__ __align__(16) uint8_t g_Bt[4 * 32768];

// ---------------------------------------------------------------------------
// Degree counting + norms
// ---------------------------------------------------------------------------
__global__ void deg_kernel(const int* __restrict__ src, const int* __restrict__ dst) {
    int e = blockIdx.x * blockDim.x + threadIdx.x;
    if (e < N_EDGES) {
        atomicAdd(&g_degout[src[e]], 1.0f);
        atomicAdd(&g_degin[dst[e]], 1.0f);
    }
}
__global__ void norm_kernel() {
    int i = blockIdx.x * blockDim.x + threadIdx.x;
    if (i < N_NODES) {
        g_outnorm[i] = rsqrtf(fmaxf(g_degout[i], 1.0f));
        g_innorm[i]  = rsqrtf(fmaxf(g_degin[i], 1.0f));
    }
}

// ---------------------------------------------------------------------------
// Edge aggregation: one warp per edge, red.global.add.v4.f32 (L2-resident)
// ---------------------------------------------------------------------------
__global__ void edge_kernel(const int* __restrict__ src, const int* __restrict__ dst,
                            const float* __restrict__ feat) {
    int t = blockIdx.x * blockDim.x + threadIdx.x;
    int e = t >> 5;
    int lane = t & 31;
    if (e < N_EDGES) {
        int s = src[e];
        int d = dst[e];
        float sc = g_outnorm[s];
        float4 v = reinterpret_cast<const float4*>(feat)[s * (DIM / 4) + lane];
        v.x *= sc; v.y *= sc; v.z *= sc; v.w *= sc;
        float* p = &g_agg[d * DIM + lane * 4];
        asm volatile("red.global.add.v4.f32 [%0], {%1, %2, %3, %4};"
                     :: "l"(p), "f"(v.x), "f"(v.y), "f"(v.z), "f"(v.w)
                     : "memory");
    }
}

// ---------------------------------------------------------------------------
// bf16 hi/lo split
// ---------------------------------------------------------------------------
__device__ __forceinline__ void split_bf16(float x, uint16_t& hi, uint16_t& lo) {
    __nv_bfloat16 h = __float2bfloat16(x);
    hi = __bfloat16_as_ushort(h);
    float hf = __uint_as_float((uint32_t)hi << 16);
    lo = __bfloat16_as_ushort(__float2bfloat16(x - hf));
}

// ---------------------------------------------------------------------------
// Prep: W[k][n] (fc_w half0, res_w half1) -> Bt[n][k] bf16 hi/lo tiles (plain)
// 4096 items: (half, n, kgroup of 8)
// ---------------------------------------------------------------------------
__global__ void prep_b_kernel(const float* __restrict__ fc_w,
                              const float* __restrict__ res_w) {
    int id = blockIdx.x * blockDim.x + threadIdx.x;   // 0..4095
    int h  = id >> 11;
    int rem = id & 2047;
    int n  = rem >> 4;
    int kb = (rem & 15) * 8;
    const float* W = h ? res_w : fc_w;
    uint32_t hp[4], lp[4];
#pragma unroll
    for (int j = 0; j < 4; j++) {
        uint16_t h0, l0, h1, l1;
        split_bf16(W[(kb + 2 * j)     * DIM + n], h0, l0);
        split_bf16(W[(kb + 2 * j + 1) * DIM + n], h1, l1);
        hp[j] = ((uint32_t)h1 << 16) | h0;
        lp[j] = ((uint32_t)l1 << 16) | l0;
    }
    uint32_t off = (uint32_t)(n * 256 + kb * 2);
    *reinterpret_cast<uint4*>(&g_Bt[(uint32_t)(h * 2)     * 32768u + off]) =
        make_uint4(hp[0], hp[1], hp[2], hp[3]);
    *reinterpret_cast<uint4*>(&g_Bt[(uint32_t)(h * 2 + 1) * 32768u + off]) =
        make_uint4(lp[0], lp[1], lp[2], lp[3]);
}

// ---------------------------------------------------------------------------
// mma.sync bf16 GEMM + bias + LayerNorm + ReLU.
// Virtual A = [agg*in_norm | feat] (M=50000, K=256), B^T tiles precomputed.
// 3-term split: Ah*Bh + Ah*Bl + Al*Bh, fp32 accumulate.
// 256 threads = 8 warps (wm 0..3 x wn 0..1): warp tile 32 rows x 64 cols.
// ---------------------------------------------------------------------------
#define ROW_BYTES 272                 // 128 bf16 = 256B + 16B pad (conflict-free)
#define TILE_BYTES (128 * ROW_BYTES)  // 34816
#define SMEM_B     0                  // 4 tiles
#define SMEM_A_HI  (4 * TILE_BYTES)
#define SMEM_A_LO  (SMEM_A_HI + TILE_BYTES)
#define SMEM_STATS (SMEM_A_LO + TILE_BYTES)   // 128 rows x 2 warps x float2
#define SMEM_TOTAL (SMEM_STATS + 2048)        // 210944

__device__ __forceinline__ uint32_t smem_u32(const void* p) {
    uint32_t a;
    asm("{ .reg .u64 t; cvta.to.shared.u64 t, %1; cvt.u32.u64 %0, t; }"
        : "=r"(a) : "l"(p));
    return a;
}
__device__ __forceinline__ void ldsm4(uint32_t (&r)[4], uint32_t addr) {
    asm volatile("ldmatrix.sync.aligned.m8n8.x4.shared.b16 {%0,%1,%2,%3}, [%4];"
                 : "=r"(r[0]), "=r"(r[1]), "=r"(r[2]), "=r"(r[3]) : "r"(addr));
}
__device__ __forceinline__ void mma16816(float (&d)[4], const uint32_t (&a)[4],
                                         uint32_t b0, uint32_t b1) {
    asm volatile("mma.sync.aligned.m16n8k16.row.col.f32.bf16.bf16.f32 "
                 "{%0,%1,%2,%3}, {%4,%5,%6,%7}, {%8,%9}, {%0,%1,%2,%3};"
                 : "+f"(d[0]), "+f"(d[1]), "+f"(d[2]), "+f"(d[3])
                 : "r"(a[0]), "r"(a[1]), "r"(a[2]), "r"(a[3]), "r"(b0), "r"(b1));
}

__global__ __launch_bounds__(256) void gemm_mma_kernel(
    const float* __restrict__ feat,
    const float* __restrict__ fc_b,
    const float* __restrict__ ln_g,
    const float* __restrict__ ln_b,
    float* __restrict__ out)
{
    extern __shared__ __align__(16) char smem[];
    const uint32_t sb = smem_u32(smem);
    const int tid  = threadIdx.x;
    const int wid  = tid >> 5;
    const int lane = tid & 31;
    const int wm   = wid & 3;        // warp row group (32 rows)
    const int wn   = wid >> 2;       // warp col group (64 cols)
    const int bm0  = blockIdx.x * 128;

    // ---- copy B tiles into padded SMEM layout (128KB from L2) ----
    {
        const uint4* src = reinterpret_cast<const uint4*>(g_Bt);
#pragma unroll
        for (int i = 0; i < 32; i++) {
            int idx = tid + i * 256;
            int t = idx >> 11, rem = idx & 2047;
            int n = rem >> 4, c = rem & 15;
            uint4 v = src[t * 2048 + n * 16 + c];
            *reinterpret_cast<uint4*>(smem + SMEM_B + t * TILE_BYTES + n * ROW_BYTES + c * 16) = v;
        }
    }

    // ---- A loader: 16 rows/pass x 8 passes; convert fp32 -> hi/lo bf16 ----
    auto load_a_half = [&](int half) {
        const float* Ap = half ? feat : g_agg;
        const int r0 = tid >> 4;
        const int kb = (tid & 15) * 8;
#pragma unroll
        for (int pass = 0; pass < 8; pass++) {
            int row_l = pass * 16 + r0;
            int row_g = bm0 + row_l;
            float x[8];
            if (row_g < N_NODES) {
                float4 v0 = *reinterpret_cast<const float4*>(Ap + (size_t)row_g * DIM + kb);
                float4 v1 = *reinterpret_cast<const float4*>(Ap + (size_t)row_g * DIM + kb + 4);
                x[0]=v0.x; x[1]=v0.y; x[2]=v0.z; x[3]=v0.w;
                x[4]=v1.x; x[5]=v1.y; x[6]=v1.z; x[7]=v1.w;
                if (half == 0) {
                    float s = g_innorm[row_g];
#pragma unroll
                    for (int j = 0; j < 8; j++) x[j] *= s;
                }
            } else {
#pragma unroll
                for (int j = 0; j < 8; j++) x[j] = 0.0f;
            }
            uint32_t hp[4], lp[4];
#pragma unroll
            for (int j = 0; j < 4; j++) {
                uint16_t h0, l0, h1, l1;
                split_bf16(x[2 * j], h0, l0);
                split_bf16(x[2 * j + 1], h1, l1);
                hp[j] = ((uint32_t)h1 << 16) | h0;
                lp[j] = ((uint32_t)l1 << 16) | l0;
            }
            uint32_t off = (uint32_t)(row_l * ROW_BYTES + kb * 2);
            *reinterpret_cast<uint4*>(smem + SMEM_A_HI + off) = make_uint4(hp[0], hp[1], hp[2], hp[3]);
            *reinterpret_cast<uint4*>(smem + SMEM_A_LO + off) = make_uint4(lp[0], lp[1], lp[2], lp[3]);
        }
    };

    float acc[2][8][4];
#pragma unroll
    for (int m = 0; m < 2; m++)
#pragma unroll
        for (int n = 0; n < 8; n++)
#pragma unroll
            for (int c = 0; c < 4; c++) acc[m][n][c] = 0.0f;

    // ldmatrix lane address pattern: rows 0-15 at +0, rows 0-15 at +16B
    const uint32_t lane_off = (uint32_t)((lane & 15) * ROW_BYTES + (lane >> 4) * 16);

    auto compute_half = [&](int half) {
        const uint32_t bhi = sb + SMEM_B + (uint32_t)(half * 2) * TILE_BYTES;
        const uint32_t blo = bhi + TILE_BYTES;
        const uint32_t ahi = sb + SMEM_A_HI + (uint32_t)(wm * 32) * ROW_BYTES;
        const uint32_t alo = sb + SMEM_A_LO + (uint32_t)(wm * 32) * ROW_BYTES;
#pragma unroll 2
        for (int ks = 0; ks < 8; ks++) {
            const uint32_t koff = (uint32_t)(ks * 32) + lane_off;
            uint32_t ah[2][4], al[2][4];
            ldsm4(ah[0], ahi + koff);
            ldsm4(ah[1], ahi + 16 * ROW_BYTES + koff);
            ldsm4(al[0], alo + koff);
            ldsm4(al[1], alo + 16 * ROW_BYTES + koff);
#pragma unroll
            for (int ng = 0; ng < 4; ng++) {
                uint32_t bh[4], bl[4];
                const uint32_t nrow = (uint32_t)((wn * 64 + ng * 16) * ROW_BYTES);
                ldsm4(bh, bhi + nrow + koff);
                ldsm4(bl, blo + nrow + koff);
#pragma unroll
                for (int m = 0; m < 2; m++) {
                    mma16816(acc[m][2 * ng],     ah[m], bh[0], bh[2]);
                    mma16816(acc[m][2 * ng + 1], ah[m], bh[1], bh[3]);
                    mma16816(acc[m][2 * ng],     ah[m], bl[0], bl[2]);
                    mma16816(acc[m][2 * ng + 1], ah[m], bl[1], bl[3]);
                    mma16816(acc[m][2 * ng],     al[m], bh[0], bh[2]);
                    mma16816(acc[m][2 * ng + 1], al[m], bh[1], bh[3]);
                }
            }
        }
    };

    load_a_half(0);
    __syncthreads();
    compute_half(0);
    __syncthreads();          // everyone done reading A half0
    load_a_half(1);
    __syncthreads();
    compute_half(1);

    // ---- epilogue: bias*in_norm, LN stats, ReLU ----
    const int r = lane >> 2, q = lane & 3;
    int rowl[4];
    float innm[4];
#pragma unroll
    for (int mf = 0; mf < 2; mf++)
#pragma unroll
        for (int s = 0; s < 2; s++) {
            int i = mf * 2 + s;
            rowl[i] = wm * 32 + mf * 16 + s * 8 + r;
            int row_g = bm0 + rowl[i];
            innm[i] = (row_g < N_NODES) ? g_innorm[row_g] : 0.0f;
        }

    float s1[4] = {0.f, 0.f, 0.f, 0.f}, s2[4] = {0.f, 0.f, 0.f, 0.f};
#pragma unroll
    for (int nf = 0; nf < 8; nf++) {
        int col = wn * 64 + nf * 8 + q * 2;
        float2 bs = *reinterpret_cast<const float2*>(fc_b + col);
#pragma unroll
        for (int mf = 0; mf < 2; mf++)
#pragma unroll
            for (int s = 0; s < 2; s++) {
                int i = mf * 2 + s;
                float x = acc[mf][nf][s * 2]     + innm[i] * bs.x;
                float y = acc[mf][nf][s * 2 + 1] + innm[i] * bs.y;
                acc[mf][nf][s * 2] = x;
                acc[mf][nf][s * 2 + 1] = y;
                s1[i] += x + y;
                s2[i] += x * x + y * y;
            }
    }
#pragma unroll
    for (int o = 1; o <= 2; o <<= 1)
#pragma unroll
        for (int i = 0; i < 4; i++) {
            s1[i] += __shfl_xor_sync(0xFFFFFFFFu, s1[i], o);
            s2[i] += __shfl_xor_sync(0xFFFFFFFFu, s2[i], o);
        }

    float2* stats = reinterpret_cast<float2*>(smem + SMEM_STATS);
    if (q == 0) {
#pragma unroll
        for (int i = 0; i < 4; i++)
            stats[rowl[i] * 2 + wn] = make_float2(s1[i], s2[i]);
    }
    __syncthreads();

    float mu[4], inv[4];
#pragma unroll
    for (int i = 0; i < 4; i++) {
        float2 a0 = stats[rowl[i] * 2];
        float2 a1 = stats[rowl[i] * 2 + 1];
        float S = a0.x + a1.x, S2 = a0.y + a1.y;
        mu[i] = S * (1.0f / DIM);
        float var = S2 * (1.0f / DIM) - mu[i] * mu[i];
        inv[i] = rsqrtf(var + LN_EPS);
    }

#pragma unroll
    for (int nf = 0; nf < 8; nf++) {
        int col = wn * 64 + nf * 8 + q * 2;
        float2 g2 = *reinterpret_cast<const float2*>(ln_g + col);
        float2 b2 = *reinterpret_cast<const float2*>(ln_b + col);
#pragma unroll
        for (int mf = 0; mf < 2; mf++)
#pragma unroll
            for (int s = 0; s < 2; s++) {
                int i = mf * 2 + s;
                int row_g = bm0 + rowl[i];
                if (row_g < N_NODES) {
                    float2 o;
                    o.x = fmaxf((acc[mf][nf][s * 2]     - mu[i]) * inv[i] * g2.x + b2.x, 0.f);
                    o.y = fmaxf((acc[mf][nf][s * 2 + 1] - mu[i]) * inv[i] * g2.y + b2.y, 0.f);
                    *reinterpret_cast<float2*>(out + (size_t)row_g * DIM + col) = o;
                }
            }
    }
}

// ---------------------------------------------------------------------------
extern "C" void kernel_launch(void* const* d_in, const int* in_sizes, int n_in,
                              void* d_out, int out_size) {
    const float* feat  = (const float*)d_in[0];
    const int*   src   = (const int*)d_in[1];
    const int*   dst   = (const int*)d_in[2];
    const float* fc_w  = (const float*)d_in[3];
    const float* fc_b  = (const float*)d_in[4];
    const float* res_w = (const float*)d_in[5];
    const float* ln_g  = (const float*)d_in[6];
    const float* ln_b  = (const float*)d_in[7];
    float* out = (float*)d_out;

    void *agg_p, *dout_p, *din_p;
    cudaGetSymbolAddress(&agg_p, g_agg);
    cudaGetSymbolAddress(&dout_p, g_degout);
    cudaGetSymbolAddress(&din_p, g_degin);
    cudaMemsetAsync(agg_p, 0, sizeof(float) * N_NODES * DIM);
    cudaMemsetAsync(dout_p, 0, sizeof(float) * N_NODES);
    cudaMemsetAsync(din_p, 0, sizeof(float) * N_NODES);

    deg_kernel<<<(N_EDGES + 255) / 256, 256>>>(src, dst);
    norm_kernel<<<(N_NODES + 255) / 256, 256>>>();
    prep_b_kernel<<<16, 256>>>(fc_w, res_w);
    edge_kernel<<<(N_EDGES * 32) / 256, 256>>>(src, dst, feat);

    cudaFuncSetAttribute(gemm_mma_kernel,
                         cudaFuncAttributeMaxDynamicSharedMemorySize, SMEM_TOTAL);
    gemm_mma_kernel<<<(N_NODES + 127) / 128, 256, SMEM_TOTAL>>>(feat, fc_b, ln_g, ln_b, out);
}